// round 1
// baseline (speedup 1.0000x reference)
#include <cuda_runtime.h>
#include <cstdint>

#define GSZ   160
#define SS    128
#define NRAYS 4096
#define MTOT  (NRAYS * SS)

// output layout (flattened tuple, f32):
// rgb    [NRAYS,3]  @ 0
// depth  [NRAYS,1]  @ 12288
// normal [NRAYS,3]  @ 16384
// acc    [NRAYS,1]  @ 28672
// grads  [M,3]      @ 32768
#define OFF_RGB    0
#define OFF_DEPTH  12288
#define OFF_NORMAL 16384
#define OFF_ACC    28672
#define OFF_GRAD   32768

__global__ void __launch_bounds__(128)
plainvoxels_kernel(const float* __restrict__ rays_o,
                   const float* __restrict__ rays_d,
                   const float* __restrict__ rays_d_norm,
                   const int*   __restrict__ ray_indices,
                   const float* __restrict__ t_nears,
                   const float* __restrict__ t_fars,
                   const float* __restrict__ grid,
                   const float* __restrict__ beta,
                   float*       __restrict__ out)
{
    const int r   = blockIdx.x;      // ray
    const int s   = threadIdx.x;     // sample within ray
    const int idx = r * SS + s;
    const int lane = s & 31;
    const int wid  = s >> 5;

    __shared__ float s_wsum[4];
    __shared__ float s_red[4][8];

    const int rid = ray_indices[idx];
    const float tn = t_nears[idx];
    const float tf = t_fars[idx];
    const float tmid = 0.5f * (tn + tf);
    const float dt   = tf - tn;

    const float ox = rays_o[rid * 3 + 0];
    const float oy = rays_o[rid * 3 + 1];
    const float oz = rays_o[rid * 3 + 2];
    const float dx = rays_d[rid * 3 + 0];
    const float dy = rays_d[rid * 3 + 1];
    const float dz = rays_d[rid * 3 + 2];

    const float px = ox + tmid * dx;
    const float py = oy + tmid * dy;
    const float pz = oz + tmid * dz;

    // u = x / CELL ; clip to [0, G-1-1e-4]; grad mask where strictly inside
    const float HI = 158.9999f;
    const float ux = px / 0.01f;
    const float uy = py / 0.01f;
    const float uz = pz / 0.01f;

    const float cux = fminf(fmaxf(ux, 0.0f), HI);
    const float cuy = fminf(fmaxf(uy, 0.0f), HI);
    const float cuz = fminf(fmaxf(uz, 0.0f), HI);

    const bool mgx = (ux > 0.0f) && (ux < HI);
    const bool mgy = (uy > 0.0f) && (uy < HI);
    const bool mgz = (uz > 0.0f) && (uz < HI);

    const int ix0 = (int)floorf(cux);
    const int iy0 = (int)floorf(cuy);
    const int iz0 = (int)floorf(cuz);

    const float fx = cux - (float)ix0;
    const float fy = cuy - (float)iy0;
    const float fz = cuz - (float)iz0;

    const float wxa[2] = {1.0f - fx, fx};
    const float wya[2] = {1.0f - fy, fy};
    const float wza[2] = {1.0f - fz, fz};

    float v0 = 0.f, v1 = 0.f, v2 = 0.f, v3 = 0.f, v4 = 0.f;
    float gx = 0.f, gy = 0.f, gz = 0.f;

    #pragma unroll
    for (int cx = 0; cx < 2; cx++) {
        #pragma unroll
        for (int cy = 0; cy < 2; cy++) {
            #pragma unroll
            for (int cz = 0; cz < 2; cz++) {
                const float* p = grid +
                    ((size_t)((ix0 + cx) * GSZ + (iy0 + cy)) * GSZ + (iz0 + cz)) * 5;
                const float a0 = __ldg(p + 0);
                const float a1 = __ldg(p + 1);
                const float a2 = __ldg(p + 2);
                const float a3 = __ldg(p + 3);
                const float a4 = __ldg(p + 4);
                const float w  = wxa[cx] * wya[cy] * wza[cz];
                v0 += a0 * w;
                v1 += a1 * w;
                v2 += a2 * w;
                v3 += a3 * w;
                v4 += a4 * w;
                const float sgnx = cx ? 1.0f : -1.0f;
                const float sgny = cy ? 1.0f : -1.0f;
                const float sgnz = cz ? 1.0f : -1.0f;
                gx += a0 * (sgnx * wya[cy] * wza[cz]);
                gy += a0 * (sgny * wxa[cx] * wza[cz]);
                gz += a0 * (sgnz * wxa[cx] * wya[cy]);
            }
        }
    }

    // world-space gradient with clip-grad masking (matches jax.grad through clip)
    gx = mgx ? (gx / 0.01f) : 0.0f;
    gy = mgy ? (gy / 0.01f) : 0.0f;
    gz = mgz ? (gz / 0.01f) : 0.0f;

    const float gnorm = sqrtf(gx * gx + gy * gy + gz * gz);
    const float ginv  = 1.0f / fmaxf(gnorm, 1e-12f);
    const float nx = gx * ginv;
    const float ny = gy * ginv;
    const float nz = gz * ginv;

    // Laplace CDF density
    const float bc    = fmaxf(beta[0], 1e-4f);
    const float alpha = 1.0f / bc;
    const float sdf   = v0;
    const float sgn   = (sdf > 0.0f) ? 1.0f : ((sdf < 0.0f) ? -1.0f : 0.0f);
    const float sigma = 0.5f * alpha * (1.0f + sgn * expm1f(-fabsf(sdf) / bc));

    const bool  mask = (v4 >= 1.0f);
    const float tau  = mask ? (sigma * dt) : 0.0f;

    // --- block-wide inclusive scan of tau over 128 samples ---
    float inc = tau;
    #pragma unroll
    for (int o = 1; o < 32; o <<= 1) {
        const float nbr = __shfl_up_sync(0xffffffffu, inc, o);
        if (lane >= o) inc += nbr;
    }
    if (lane == 31) s_wsum[wid] = inc;
    __syncthreads();
    float woff = 0.0f;
    #pragma unroll
    for (int wI = 0; wI < 4; wI++)
        if (wI < wid) woff += s_wsum[wI];
    const float excl  = (inc + woff) - tau;
    const float trans = expf(-excl);
    float wgt = trans * (-expm1f(-tau));
    if (!mask) wgt = 0.0f;

    // per-point gradient output (masked)
    const float ogx = mask ? gx : 0.0f;
    const float ogy = mask ? gy : 0.0f;
    const float ogz = mask ? gz : 0.0f;
    out[OFF_GRAD + (size_t)idx * 3 + 0] = ogx;
    out[OFF_GRAD + (size_t)idx * 3 + 1] = ogy;
    out[OFF_GRAD + (size_t)idx * 3 + 2] = ogz;

    // --- per-ray reductions: rgb(3), depth, normal(3), acc ---
    float acc8[8];
    acc8[0] = wgt * v1;
    acc8[1] = wgt * v2;
    acc8[2] = wgt * v3;
    acc8[3] = wgt * tmid;
    acc8[4] = wgt * nx;
    acc8[5] = wgt * ny;
    acc8[6] = wgt * nz;
    acc8[7] = wgt;

    #pragma unroll
    for (int k = 0; k < 8; k++) {
        #pragma unroll
        for (int o = 16; o > 0; o >>= 1)
            acc8[k] += __shfl_down_sync(0xffffffffu, acc8[k], o);
    }
    if (lane == 0) {
        #pragma unroll
        for (int k = 0; k < 8; k++) s_red[wid][k] = acc8[k];
    }
    __syncthreads();

    if (s < 8) {
        const float sum = s_red[0][s] + s_red[1][s] + s_red[2][s] + s_red[3][s];
        if (s < 3) {
            out[OFF_RGB + r * 3 + s] = sum;
        } else if (s == 3) {
            out[OFF_DEPTH + r] = sum / rays_d_norm[r];
        } else if (s < 7) {
            out[OFF_NORMAL + r * 3 + (s - 4)] = sum;
        } else {
            out[OFF_ACC + r] = sum;
        }
    }
}

extern "C" void kernel_launch(void* const* d_in, const int* in_sizes, int n_in,
                              void* d_out, int out_size)
{
    const float* rays_o      = (const float*)d_in[0];
    const float* rays_d      = (const float*)d_in[1];
    const float* rays_d_norm = (const float*)d_in[2];
    const int*   ray_indices = (const int*)  d_in[3];
    const float* t_nears     = (const float*)d_in[4];
    const float* t_fars      = (const float*)d_in[5];
    const float* grid        = (const float*)d_in[6];
    const float* beta        = (const float*)d_in[7];
    float* out = (float*)d_out;

    plainvoxels_kernel<<<NRAYS, SS>>>(rays_o, rays_d, rays_d_norm, ray_indices,
                                      t_nears, t_fars, grid, beta, out);
}

// round 2
// speedup vs baseline: 1.2110x; 1.2110x over previous
#include <cuda_runtime.h>
#include <cstdint>

#define GSZ   160
#define SS    128
#define NRAYS 4096

#define OFF_RGB    0
#define OFF_DEPTH  12288
#define OFF_NORMAL 16384
#define OFF_ACC    28672
#define OFF_GRAD   32768

__global__ void __launch_bounds__(128)
plainvoxels_kernel(const float* __restrict__ rays_o,
                   const float* __restrict__ rays_d,
                   const float* __restrict__ rays_d_norm,
                   const int*   __restrict__ ray_indices,
                   const float* __restrict__ t_nears,
                   const float* __restrict__ t_fars,
                   const float* __restrict__ grid,
                   const float* __restrict__ beta,
                   float*       __restrict__ out)
{
    const int r   = blockIdx.x;
    const int s   = threadIdx.x;
    const int idx = r * SS + s;
    const int lane = s & 31;
    const int wid  = s >> 5;

    __shared__ float s_wsum[4];
    __shared__ float s_red[4][8];

    const int rid = ray_indices[idx];
    const float tn = t_nears[idx];
    const float tf = t_fars[idx];
    const float tmid = 0.5f * (tn + tf);
    const float dt   = tf - tn;

    const float ox = rays_o[rid * 3 + 0];
    const float oy = rays_o[rid * 3 + 1];
    const float oz = rays_o[rid * 3 + 2];
    const float dx = rays_d[rid * 3 + 0];
    const float dy = rays_d[rid * 3 + 1];
    const float dz = rays_d[rid * 3 + 2];

    const float px = ox + tmid * dx;
    const float py = oy + tmid * dy;
    const float pz = oz + tmid * dz;

    const float HI = 158.9999f;
    const float ux = px / 0.01f;
    const float uy = py / 0.01f;
    const float uz = pz / 0.01f;

    const float cux = fminf(fmaxf(ux, 0.0f), HI);
    const float cuy = fminf(fmaxf(uy, 0.0f), HI);
    const float cuz = fminf(fmaxf(uz, 0.0f), HI);

    const bool mgx = (ux > 0.0f) && (ux < HI);
    const bool mgy = (uy > 0.0f) && (uy < HI);
    const bool mgz = (uz > 0.0f) && (uz < HI);

    const int ix0 = (int)floorf(cux);
    const int iy0 = (int)floorf(cuy);
    const int iz0 = (int)floorf(cuz);

    const float fx = cux - (float)ix0;
    const float fy = cuy - (float)iy0;
    const float fz = cuz - (float)iz0;

    const float wxa[2] = {1.0f - fx, fx};
    const float wya[2] = {1.0f - fy, fy};
    const float wz0 = 1.0f - fz;
    const float wz1 = fz;

    float v0 = 0.f, v1 = 0.f, v2 = 0.f, v3 = 0.f, v4 = 0.f;
    float gx = 0.f, gy = 0.f, gz = 0.f;

    // 4 (x,y) corner columns; each covers z0 and z0+1 cells = 10 contiguous floats
    #pragma unroll
    for (int cx = 0; cx < 2; cx++) {
        #pragma unroll
        for (int cy = 0; cy < 2; cy++) {
            const int cidx = (((ix0 + cx) * GSZ + (iy0 + cy)) * GSZ + iz0) * 5; // float index
            const int al = cidx & ~3;           // 16B-aligned float index
            const int o  = cidx & 3;            // 0..3
            const float4* p4 = (const float4*)(grid + al);
            const float4 q0 = __ldg(p4 + 0);
            const float4 q1 = __ldg(p4 + 1);
            const float4 q2 = __ldg(p4 + 2);
            float4 q3 = q2;
            if (o == 3) q3 = __ldg(p4 + 3);     // only needed (and in-bounds) when o==3

            float w16[16];
            w16[0]=q0.x; w16[1]=q0.y; w16[2]=q0.z; w16[3]=q0.w;
            w16[4]=q1.x; w16[5]=q1.y; w16[6]=q1.z; w16[7]=q1.w;
            w16[8]=q2.x; w16[9]=q2.y; w16[10]=q2.z; w16[11]=q2.w;
            w16[12]=q3.x; w16[13]=q3.y; w16[14]=q3.z; w16[15]=q3.w;

            float b[10];
            #pragma unroll
            for (int k = 0; k < 10; k++) {
                const float e0 = w16[k];
                const float e1 = w16[k + 1];
                const float e2 = w16[k + 2];
                const float e3 = w16[k + 3];
                b[k] = (o == 0) ? e0 : (o == 1) ? e1 : (o == 2) ? e2 : e3;
            }
            // b[0..4] = cell(z0) channels, b[5..9] = cell(z0+1) channels

            const float wxy = wxa[cx] * wya[cy];
            const float w0  = wxy * wz0;
            const float w1  = wxy * wz1;

            v0 += b[0] * w0 + b[5] * w1;
            v1 += b[1] * w0 + b[6] * w1;
            v2 += b[2] * w0 + b[7] * w1;
            v3 += b[3] * w0 + b[8] * w1;
            v4 += b[4] * w0 + b[9] * w1;

            const float a0z = b[0] * wz0 + b[5] * wz1;   // z-interp of sdf channel
            const float sgnx = cx ? 1.0f : -1.0f;
            const float sgny = cy ? 1.0f : -1.0f;
            gx += a0z * (sgnx * wya[cy]);
            gy += a0z * (sgny * wxa[cx]);
            gz += wxy * (b[5] - b[0]);
        }
    }

    gx = mgx ? (gx / 0.01f) : 0.0f;
    gy = mgy ? (gy / 0.01f) : 0.0f;
    gz = mgz ? (gz / 0.01f) : 0.0f;

    const float gnorm = sqrtf(gx * gx + gy * gy + gz * gz);
    const float ginv  = 1.0f / fmaxf(gnorm, 1e-12f);
    const float nx = gx * ginv;
    const float ny = gy * ginv;
    const float nz = gz * ginv;

    const float bc    = fmaxf(beta[0], 1e-4f);
    const float alpha = 1.0f / bc;
    const float sdf   = v0;
    const float sgn   = (sdf > 0.0f) ? 1.0f : ((sdf < 0.0f) ? -1.0f : 0.0f);
    const float sigma = 0.5f * alpha * (1.0f + sgn * expm1f(-fabsf(sdf) / bc));

    const bool  mask = (v4 >= 1.0f);
    const float tau  = mask ? (sigma * dt) : 0.0f;

    // block-wide inclusive scan of tau
    float inc = tau;
    #pragma unroll
    for (int o2 = 1; o2 < 32; o2 <<= 1) {
        const float nbr = __shfl_up_sync(0xffffffffu, inc, o2);
        if (lane >= o2) inc += nbr;
    }
    if (lane == 31) s_wsum[wid] = inc;
    __syncthreads();
    float woff = 0.0f;
    #pragma unroll
    for (int wI = 0; wI < 4; wI++)
        if (wI < wid) woff += s_wsum[wI];
    const float excl  = (inc + woff) - tau;
    const float trans = expf(-excl);
    float wgt = trans * (-expm1f(-tau));
    if (!mask) wgt = 0.0f;

    const float ogx = mask ? gx : 0.0f;
    const float ogy = mask ? gy : 0.0f;
    const float ogz = mask ? gz : 0.0f;
    out[OFF_GRAD + idx * 3 + 0] = ogx;
    out[OFF_GRAD + idx * 3 + 1] = ogy;
    out[OFF_GRAD + idx * 3 + 2] = ogz;

    float acc8[8];
    acc8[0] = wgt * v1;
    acc8[1] = wgt * v2;
    acc8[2] = wgt * v3;
    acc8[3] = wgt * tmid;
    acc8[4] = wgt * nx;
    acc8[5] = wgt * ny;
    acc8[6] = wgt * nz;
    acc8[7] = wgt;

    #pragma unroll
    for (int k = 0; k < 8; k++) {
        #pragma unroll
        for (int o2 = 16; o2 > 0; o2 >>= 1)
            acc8[k] += __shfl_down_sync(0xffffffffu, acc8[k], o2);
    }
    if (lane == 0) {
        #pragma unroll
        for (int k = 0; k < 8; k++) s_red[wid][k] = acc8[k];
    }
    __syncthreads();

    if (s < 8) {
        const float sum = s_red[0][s] + s_red[1][s] + s_red[2][s] + s_red[3][s];
        if (s < 3) {
            out[OFF_RGB + r * 3 + s] = sum;
        } else if (s == 3) {
            out[OFF_DEPTH + r] = sum / rays_d_norm[r];
        } else if (s < 7) {
            out[OFF_NORMAL + r * 3 + (s - 4)] = sum;
        } else {
            out[OFF_ACC + r] = sum;
        }
    }
}

extern "C" void kernel_launch(void* const* d_in, const int* in_sizes, int n_in,
                              void* d_out, int out_size)
{
    const float* rays_o      = (const float*)d_in[0];
    const float* rays_d      = (const float*)d_in[1];
    const float* rays_d_norm = (const float*)d_in[2];
    const int*   ray_indices = (const int*)  d_in[3];
    const float* t_nears     = (const float*)d_in[4];
    const float* t_fars      = (const float*)d_in[5];
    const float* grid        = (const float*)d_in[6];
    const float* beta        = (const float*)d_in[7];
    float* out = (float*)d_out;

    plainvoxels_kernel<<<NRAYS, SS>>>(rays_o, rays_d, rays_d_norm, ray_indices,
                                      t_nears, t_fars, grid, beta, out);
}